// round 15
// baseline (speedup 1.0000x reference)
#include <cuda_runtime.h>
#include <cuda_fp16.h>
#include <cstdint>

#define BATCH 2
#define SEQ 2048
#define NEMBD 1024
#define NHEAD 16
#define HDIM 64
#define WINDOW 256
#define ATT_SCALE 0.125f   // 1/sqrt(64)

// ---------------- device scratch (allocation-free rule) ----------------
__device__ __half g_kvh[(size_t)4096 * 3072];      // qkv fp16
__device__ __half g_ah[(size_t)4096 * 1024];       // hidden fp16
__device__ __half g_wh[(size_t)1024 * 3072];       // w_attn fp16 [K,N]
__device__ __half g_ph[(size_t)1024 * 1024];       // w_proj fp16 [K,N]
__device__ __half g_oh[(size_t)4096 * 1024];       // attn out fp16

// ---------------- helpers ----------------
__device__ __forceinline__ uint32_t smem_u32(const void* p) {
    uint32_t a;
    asm("{ .reg .u64 t; cvta.to.shared.u64 t, %1; cvt.u32.u64 %0, t; }"
        : "=r"(a) : "l"(p));
    return a;
}
__device__ __forceinline__ uint32_t pkh2(float a, float b) {
    __half2 h = __floats2half2_rn(a, b);
    return *(uint32_t*)&h;
}
__device__ __forceinline__ void mma16816h(float* c, const uint32_t* a, const uint32_t* b) {
    asm volatile(
        "mma.sync.aligned.m16n8k16.row.col.f32.f16.f16.f32 "
        "{%0,%1,%2,%3},{%4,%5,%6,%7},{%8,%9},{%0,%1,%2,%3};"
        : "+f"(c[0]), "+f"(c[1]), "+f"(c[2]), "+f"(c[3])
        : "r"(a[0]), "r"(a[1]), "r"(a[2]), "r"(a[3]), "r"(b[0]), "r"(b[1]));
}
__device__ __forceinline__ void ldsm4(uint32_t* r, uint32_t addr) {
    asm volatile("ldmatrix.sync.aligned.m8n8.x4.shared.b16 {%0,%1,%2,%3}, [%4];"
                 : "=r"(r[0]), "=r"(r[1]), "=r"(r[2]), "=r"(r[3]) : "r"(addr));
}
__device__ __forceinline__ void ldsm4t(uint32_t* r, uint32_t addr) {
    asm volatile("ldmatrix.sync.aligned.m8n8.x4.trans.shared.b16 {%0,%1,%2,%3}, [%4];"
                 : "=r"(r[0]), "=r"(r[1]), "=r"(r[2]), "=r"(r[3]) : "r"(addr));
}
__device__ __forceinline__ void cpa16(uint32_t saddr, const void* gaddr) {
    asm volatile("cp.async.cg.shared.global [%0], [%1], 16;" :: "r"(saddr), "l"(gaddr));
}
#define CP_COMMIT() asm volatile("cp.async.commit_group;")
#define CP_WAIT0()  asm volatile("cp.async.wait_group 0;")
#define CP_WAIT1()  asm volatile("cp.async.wait_group 1;")

// SW128 swizzle for 128B rows
__device__ __forceinline__ uint32_t swz(int row, int col) {
    return (uint32_t)(row * 128 + (col ^ ((row & 7) << 4)));
}
__device__ __forceinline__ float qmax(float v) {
    v = fmaxf(v, __shfl_xor_sync(0xFFFFFFFFu, v, 1));
    v = fmaxf(v, __shfl_xor_sync(0xFFFFFFFFu, v, 2));
    return v;
}
__device__ __forceinline__ float qsum(float v) {
    v += __shfl_xor_sync(0xFFFFFFFFu, v, 1);
    v += __shfl_xor_sync(0xFFFFFFFFu, v, 2);
    return v;
}

// ===========================================================================
// merged fp32 -> fp16 conversion: hidden | w_attn | w_proj in ONE launch
// ===========================================================================
#define CVT_N1 (4096 * 1024 / 4)
#define CVT_N2 (1024 * 3072 / 4)
#define CVT_N3 (1024 * 1024 / 4)

__global__ void cvt_all_kernel(const float* __restrict__ s1, __half* __restrict__ d1,
                               const float* __restrict__ s2, __half* __restrict__ d2,
                               const float* __restrict__ s3, __half* __restrict__ d3) {
    int i = blockIdx.x * blockDim.x + threadIdx.x;
    const float* src; __half* dst;
    if (i < CVT_N1)                { src = s1; dst = d1; }
    else if (i < CVT_N1 + CVT_N2)  { src = s2; dst = d2; i -= CVT_N1; }
    else if (i < CVT_N1 + CVT_N2 + CVT_N3) { src = s3; dst = d3; i -= CVT_N1 + CVT_N2; }
    else return;
    float4 v = *(const float4*)(src + (size_t)i * 4);
    uint2 o;
    o.x = pkh2(v.x, v.y);
    o.y = pkh2(v.z, v.w);
    *(uint2*)(dst + (size_t)i * 4) = o;
}

// ===========================================================================
// QKV GEMM (R13 config, unchanged): CTA 128M x 64N, 256 threads, fp16 out.
// ===========================================================================
#define Q_ST_A  0
#define Q_ST_B  16384
#define Q_ST_SZ 24576
#define QSMEM   (2 * Q_ST_SZ)

__global__ __launch_bounds__(256, 1)
void gemm_qkv_kernel(const __half* __restrict__ A, const __half* __restrict__ B,
                     const float* __restrict__ bias, __half* __restrict__ Ch,
                     int M, int N, int K) {
    extern __shared__ char sm[];
    const uint32_t sb = smem_u32(sm);
    const int tid = threadIdx.x, lane = tid & 31, wid = tid >> 5;
    const int m0 = blockIdx.y * 128, n0 = blockIdx.x * 64;
    const int wm = wid >> 1, wn = wid & 1;
    const int l15 = lane & 15, chi = (lane >> 4) * 16;
    const int lrow = tid >> 3, lc = tid & 7;
    const int NT = K / 64;

    float acc[2][4][4];
#pragma unroll
    for (int i = 0; i < 2; i++)
#pragma unroll
        for (int j = 0; j < 4; j++)
#pragma unroll
            for (int r = 0; r < 4; r++) acc[i][j][r] = 0.f;

    auto load_stage = [&](int s, int kt) {
        const uint32_t sbase = sb + s * Q_ST_SZ;
        const size_t gk = (size_t)kt * 64 + lc * 8;
#pragma unroll
        for (int i = 0; i < 4; i++) {
            const int row = lrow + i * 32;
            cpa16(sbase + Q_ST_A + swz(row, lc * 16), A + (size_t)(m0 + row) * K + gk);
        }
#pragma unroll
        for (int i = 0; i < 2; i++) {
            const int c = tid + i * 256;
            const int r = c >> 3;
            const int nch = c & 7;
            cpa16(sbase + Q_ST_B + swz(r, nch * 16),
                  B + (size_t)(kt * 64 + r) * N + n0 + nch * 8);
        }
    };

    uint32_t Af[2][2][4], Bf[2][2][4];
    auto load_frags = [&](int fb, uint32_t abase, int ks) {
        const int cb = ks * 32 + chi;
#pragma unroll
        for (int mt = 0; mt < 2; mt++)
            ldsm4(Af[fb][mt], abase + Q_ST_A + swz(wm * 32 + mt * 16 + l15, cb));
        const int bcol = wn * 64;
#pragma unroll
        for (int sub = 0; sub < 2; sub++)
            ldsm4t(Bf[fb][sub], abase + Q_ST_B + swz(ks * 16 + l15, bcol + sub * 32 + chi));
    };

    load_stage(0, 0); CP_COMMIT();
    load_stage(1, 1); CP_COMMIT();

    for (int t = 0; t < NT; t++) {
        const int s = t & 1;
        CP_WAIT1();
        __syncthreads();

        const uint32_t abase = sb + s * Q_ST_SZ;
        load_frags(0, abase, 0);
#pragma unroll
        for (int ks = 0; ks < 4; ks++) {
            const int cur = ks & 1;
            if (ks < 3) load_frags(cur ^ 1, abase, ks + 1);
#pragma unroll
            for (int mt = 0; mt < 2; mt++)
#pragma unroll
                for (int nt = 0; nt < 4; nt++) {
                    uint32_t b[2] = { Bf[cur][nt >> 1][(nt & 1) * 2],
                                      Bf[cur][nt >> 1][(nt & 1) * 2 + 1] };
                    mma16816h(acc[mt][nt], Af[cur][mt], b);
                }
        }
        __syncthreads();
        if (t + 2 < NT) { load_stage(s, t + 2); CP_COMMIT(); }
    }

    const int g = lane >> 2, tig = lane & 3;
#pragma unroll
    for (int mt = 0; mt < 2; mt++) {
#pragma unroll
        for (int nt = 0; nt < 4; nt++) {
            int row0 = m0 + wm * 32 + mt * 16 + g;
            int col  = n0 + wn * 32 + nt * 8 + tig * 2;
            float2 bb = *(const float2*)(bias + col);
            *(uint32_t*)(Ch + (size_t)row0 * N + col) =
                pkh2(acc[mt][nt][0] + bb.x, acc[mt][nt][1] + bb.y);
            *(uint32_t*)(Ch + (size_t)(row0 + 8) * N + col) =
                pkh2(acc[mt][nt][2] + bb.x, acc[mt][nt][3] + bb.y);
        }
    }
}

// ===========================================================================
// proj GEMM (R13 config, reverted): CTA 128x128, 256 threads, fp32 out.
// ===========================================================================
#define ST_A  0
#define ST_B  16384
#define ST_SZ 32768
#define GSMEM (2 * ST_SZ)

__global__ __launch_bounds__(256, 1)
void gemm_h_kernel(const __half* __restrict__ A, const __half* __restrict__ B,
                   const float* __restrict__ bias, float* __restrict__ C,
                   int M, int N, int K) {
    extern __shared__ char sm[];
    const uint32_t sb = smem_u32(sm);
    const int tid = threadIdx.x, lane = tid & 31, wid = tid >> 5;
    const int m0 = blockIdx.y * 128, n0 = blockIdx.x * 128;
    const int wm = wid >> 2, wn = wid & 3;
    const int l15 = lane & 15, chi = (lane >> 4) * 16;
    const int lrow = tid >> 3, lc = tid & 7;
    const int NT = K / 64;

    float acc[4][4][4];
#pragma unroll
    for (int i = 0; i < 4; i++)
#pragma unroll
        for (int j = 0; j < 4; j++)
#pragma unroll
            for (int r = 0; r < 4; r++) acc[i][j][r] = 0.f;

    auto load_stage = [&](int s, int kt) {
        const uint32_t sbase = sb + s * ST_SZ;
        const size_t gk = (size_t)kt * 64 + lc * 8;
#pragma unroll
        for (int i = 0; i < 4; i++) {
            const int row = lrow + i * 32;
            cpa16(sbase + ST_A + swz(row, lc * 16), A + (size_t)(m0 + row) * K + gk);
        }
#pragma unroll
        for (int i = 0; i < 4; i++) {
            const int c = tid + i * 256;
            const int r = c >> 4;
            const int nch = c & 15;
            const uint32_t so = ST_B + (nch >> 3) * 8192 + swz(r, (nch & 7) * 16);
            cpa16(sbase + so, B + (size_t)(kt * 64 + r) * N + n0 + nch * 8);
        }
    };

    uint32_t Af[2][4][4], Bf[2][2][4];
    auto load_frags = [&](int fb, uint32_t abase, int ks) {
        const int cb = ks * 32 + chi;
#pragma unroll
        for (int mt = 0; mt < 4; mt++)
            ldsm4(Af[fb][mt], abase + ST_A + swz(wm * 64 + mt * 16 + l15, cb));
        const uint32_t bbase = abase + ST_B + (wn >> 1) * 8192;
        const int bcol = (wn & 1) * 64;
#pragma unroll
        for (int sub = 0; sub < 2; sub++)
            ldsm4t(Bf[fb][sub], bbase + swz(ks * 16 + l15, bcol + sub * 32 + chi));
    };

    load_stage(0, 0); CP_COMMIT();
    load_stage(1, 1); CP_COMMIT();

    for (int t = 0; t < NT; t++) {
        const int s = t & 1;
        CP_WAIT1();
        __syncthreads();

        const uint32_t abase = sb + s * ST_SZ;
        load_frags(0, abase, 0);
#pragma unroll
        for (int ks = 0; ks < 4; ks++) {
            const int cur = ks & 1;
            if (ks < 3) load_frags(cur ^ 1, abase, ks + 1);
#pragma unroll
            for (int mt = 0; mt < 4; mt++)
#pragma unroll
                for (int nt = 0; nt < 4; nt++) {
                    uint32_t b[2] = { Bf[cur][nt >> 1][(nt & 1) * 2],
                                      Bf[cur][nt >> 1][(nt & 1) * 2 + 1] };
                    mma16816h(acc[mt][nt], Af[cur][mt], b);
                }
        }
        __syncthreads();
        if (t + 2 < NT) { load_stage(s, t + 2); CP_COMMIT(); }
    }

    const int g = lane >> 2, tig = lane & 3;
#pragma unroll
    for (int mt = 0; mt < 4; mt++) {
#pragma unroll
        for (int nt = 0; nt < 4; nt++) {
            int row0 = m0 + wm * 64 + mt * 16 + g;
            int col  = n0 + wn * 32 + nt * 8 + tig * 2;
            float2 bb = *(const float2*)(bias + col);
            *(float2*)(C + (size_t)row0 * N + col) =
                make_float2(acc[mt][nt][0] + bb.x, acc[mt][nt][1] + bb.y);
            *(float2*)(C + (size_t)(row0 + 8) * N + col) =
                make_float2(acc[mt][nt][2] + bb.x, acc[mt][nt][3] + bb.y);
        }
    }
}

// ===========================================================================
// Flash attention: 128 queries per CTA, 8 warps, 256 threads.
// R13 masked path (with clamp) applied to EVERY tile. m initialized to 0
// so fully-masked tiles contribute exactly 0 (exp(-1e30 - max(0,.)) == 0).
// ===========================================================================
#define AQ_OFF  0                              // Q staging: 16KB (128 rows)
#define AS_OFF  16384                          // stage s at 16384 + s*16384
#define AS_SZ   16384                          // K (8KB) + V (8KB)
#define A_SMEM  (16384 + 2 * 16384)            // 49152

__global__ __launch_bounds__(256)
void attn_mma_kernel(const __half* __restrict__ qkv, __half* __restrict__ oh) {
    extern __shared__ char sm[];
    const uint32_t sb = smem_u32(sm);
    const int b = blockIdx.z, h = blockIdx.y, qs = blockIdx.x * 128;
    const int tid = threadIdx.x, lane = tid & 31, wid = tid >> 5;   // wid 0..7
    const int l15 = lane & 15, chi = (lane >> 4) * 16;
    const int g = lane >> 2, tig = lane & 3;
    const size_t RS = 3 * NEMBD;
    const int hcol = h * HDIM;

    const int kt0 = (qs - WINDOW < 0) ? 0 : qs - WINDOW;
    const int ktend = qs + 64;                 // last tile (rows up to qs+127)
    const int ntiles = (ktend - kt0) / 64 + 1;

    // K/V tile async load into stage s (buf: 0 K, 1 V); 1024 chunks, 256 thr
    auto load_kv = [&](int s, int kt) {
        const uint32_t sbase = sb + AS_OFF + s * AS_SZ;
#pragma unroll
        for (int i = 0; i < 4; i++) {
            int idx = tid + i * 256;               // 0..1023
            int buf = idx >> 9;                    // 0 K, 1 V
            int rem = idx & 511;
            int r = rem >> 3, c = rem & 7;
            const __half* src = qkv
                + ((size_t)(b * SEQ + kt + r)) * RS + NEMBD + buf * NEMBD + hcol + c * 8;
            cpa16(sbase + buf * 8192 + swz(r, c * 16), src);
        }
    };

    load_kv(0, kt0); CP_COMMIT();
    // stage Q (128 rows x 128B = 1024 chunks) while K/V flies
#pragma unroll
    for (int i = 0; i < 4; i++) {
        int idx = tid + i * 256;                   // 0..1023
        int r = idx >> 3, c = idx & 7;
        const __half* src = qkv + ((size_t)(b * SEQ + qs + r)) * RS + hcol + c * 8;
        *(uint4*)(sm + AQ_OFF + swz(r, c * 16)) = *(const uint4*)src;
    }
    __syncthreads();
    uint32_t Qf[4][4];
#pragma unroll
    for (int kk = 0; kk < 4; kk++)
        ldsm4(Qf[kk], sb + AQ_OFF + swz(wid * 16 + l15, kk * 32 + chi));

    float o[8][4];
#pragma unroll
    for (int i = 0; i < 8; i++)
#pragma unroll
        for (int r = 0; r < 4; r++) o[i][r] = 0.f;
    // m init 0 (not -1e30): masked-only tiles then give exp(-1e30 - m) == 0
    // exactly. Softmax shift becomes max(0, rowmax) — shift-invariant, and
    // |s| <= ~4 so exp stays in range either way.
    float m0 = 0.f, m1 = 0.f, l0 = 0.f, l1 = 0.f;
    const int row0 = qs + wid * 16 + g, row1 = row0 + 8;

    for (int it = 0; it < ntiles; it++) {
        const int kt = kt0 + it * 64;
        const int cur = it & 1;
        const bool pf = (it + 1 < ntiles);
        if (pf) { load_kv(cur ^ 1, kt + 64); CP_COMMIT(); }
        if (pf) { CP_WAIT1(); } else { CP_WAIT0(); }
        __syncthreads();

        const uint32_t kbase = sb + AS_OFF + cur * AS_SZ;

        // ---- S = Q K^T ----
        float s[8][4];
#pragma unroll
        for (int i = 0; i < 8; i++)
#pragma unroll
            for (int r = 0; r < 4; r++) s[i][r] = 0.f;
#pragma unroll
        for (int kk = 0; kk < 4; kk++) {
            const int cb = kk * 32 + chi;
            uint32_t Kf[4][4];
#pragma unroll
            for (int bt = 0; bt < 4; bt++)
                ldsm4(Kf[bt], kbase + swz(bt * 16 + l15, cb));
#pragma unroll
            for (int nt = 0; nt < 8; nt++) {
                uint32_t bfr[2] = { Kf[nt >> 1][nt & 1], Kf[nt >> 1][(nt & 1) + 2] };
                mma16816h(s[nt], Qf[kk], bfr);
            }
        }

        // ---- mask (R13 path, clamp kept) + online softmax ----
        float mx0 = -1e30f, mx1 = -1e30f;
#pragma unroll
        for (int nt = 0; nt < 8; nt++) {
            int j0 = kt + nt * 8 + tig * 2, j1 = j0 + 1;
            float v;
            v = fminf(fmaxf(s[nt][0] * ATT_SCALE, -10000.f), 10000.f);
            v = (j0 <= row0 && j0 > row0 - WINDOW) ? v : -1e30f;
            s[nt][0] = v; mx0 = fmaxf(mx0, v);
            v = fminf(fmaxf(s[nt][1] * ATT_SCALE, -10000.f), 10000.f);
            v = (j1 <= row0 && j1 > row0 - WINDOW) ? v : -1e30f;
            s[nt][1] = v; mx0 = fmaxf(mx0, v);
            v = fminf(fmaxf(s[nt][2] * ATT_SCALE, -10000.f), 10000.f);
            v = (j0 <= row1 && j0 > row1 - WINDOW) ? v : -1e30f;
            s[nt][2] = v; mx1 = fmaxf(mx1, v);
            v = fminf(fmaxf(s[nt][3] * ATT_SCALE, -10000.f), 10000.f);
            v = (j1 <= row1 && j1 > row1 - WINDOW) ? v : -1e30f;
            s[nt][3] = v; mx1 = fmaxf(mx1, v);
        }
        mx0 = qmax(mx0); mx1 = qmax(mx1);
        const float m0n = fmaxf(m0, mx0), m1n = fmaxf(m1, mx1);   // >= 0 always
        const float c0 = __expf(m0 - m0n), c1 = __expf(m1 - m1n);

        uint32_t ph01[8], ph23[8];
        float sum0 = 0.f, sum1 = 0.f;
#pragma unroll
        for (int nt = 0; nt < 8; nt++) {
            float p0 = __expf(s[nt][0] - m0n), p1 = __expf(s[nt][1] - m0n);
            float p2 = __expf(s[nt][2] - m1n), p3 = __expf(s[nt][3] - m1n);
            sum0 += p0 + p1; sum1 += p2 + p3;
            ph01[nt] = pkh2(p0, p1);
            ph23[nt] = pkh2(p2, p3);
        }
        sum0 = qsum(sum0); sum1 = qsum(sum1);
        l0 = l0 * c0 + sum0; l1 = l1 * c1 + sum1;
        m0 = m0n; m1 = m1n;
#pragma unroll
        for (int i = 0; i < 8; i++) {
            o[i][0] *= c0; o[i][1] *= c0; o[i][2] *= c1; o[i][3] *= c1;
        }

        // ---- O += P V ----
#pragma unroll
        for (int kk = 0; kk < 4; kk++) {
            uint32_t pa[4] = { ph01[2 * kk], ph23[2 * kk], ph01[2 * kk + 1], ph23[2 * kk + 1] };
            uint32_t Vf[4][4];
#pragma unroll
            for (int db = 0; db < 4; db++)
                ldsm4t(Vf[db], kbase + 8192 + swz(kk * 16 + l15, db * 32 + chi));
#pragma unroll
            for (int dnt = 0; dnt < 8; dnt++) {
                uint32_t bfr[2] = { Vf[dnt >> 1][(dnt & 1) * 2], Vf[dnt >> 1][(dnt & 1) * 2 + 1] };
                mma16816h(o[dnt], pa, bfr);
            }
        }
        __syncthreads();
    }

    const float i0 = 1.f / l0, i1 = 1.f / l1;
    const size_t tok0 = (size_t)(b * SEQ) + row0;
#pragma unroll
    for (int dnt = 0; dnt < 8; dnt++) {
        int col = hcol + dnt * 8 + tig * 2;
        *(uint32_t*)(oh + tok0 * NEMBD + col)       = pkh2(o[dnt][0] * i0, o[dnt][1] * i0);
        *(uint32_t*)(oh + (tok0 + 8) * NEMBD + col) = pkh2(o[dnt][2] * i1, o[dnt][3] * i1);
    }
}

// ---------------------------------------------------------------------------
extern "C" void kernel_launch(void* const* d_in, const int* in_sizes, int n_in,
                              void* d_out, int out_size) {
    const float* hidden = (const float*)d_in[0];
    const float* w_attn = (const float*)d_in[1];
    const float* b_attn = (const float*)d_in[2];
    const float* w_proj = (const float*)d_in[3];
    const float* b_proj = (const float*)d_in[4];
    float* out = (float*)d_out;

    __half *kvh, *ah, *wh, *ph, *oh;
    cudaGetSymbolAddress((void**)&kvh, g_kvh);
    cudaGetSymbolAddress((void**)&ah, g_ah);
    cudaGetSymbolAddress((void**)&wh, g_wh);
    cudaGetSymbolAddress((void**)&ph, g_ph);
    cudaGetSymbolAddress((void**)&oh, g_oh);

    const int M = BATCH * SEQ;       // 4096
    const int E = NEMBD;             // 1024

    cudaFuncSetAttribute(gemm_qkv_kernel,
                         cudaFuncAttributeMaxDynamicSharedMemorySize, QSMEM);
    cudaFuncSetAttribute(gemm_h_kernel,
                         cudaFuncAttributeMaxDynamicSharedMemorySize, GSMEM);
    cudaFuncSetAttribute(attn_mma_kernel,
                         cudaFuncAttributeMaxDynamicSharedMemorySize, A_SMEM);

    // 0) all conversions in one launch
    {
        int total = CVT_N1 + CVT_N2 + CVT_N3;
        cvt_all_kernel<<<(total + 255) / 256, 256>>>(hidden, ah, w_attn, wh, w_proj, ph);
    }

    // 1) QKV projection (128x64 tiles)
    gemm_qkv_kernel<<<dim3(3 * E / 64, M / 128), 256, QSMEM>>>(
        ah, wh, b_attn, kvh, M, 3 * E, E);
    // 2) flash attention (128 queries/CTA) -> fp16
    attn_mma_kernel<<<dim3(SEQ / 128, NHEAD, BATCH), 256, A_SMEM>>>(kvh, oh);
    // 3) output projection (128x128 tiles, R13-proven) -> fp32
    gemm_h_kernel<<<dim3(E / 128, M / 128), 256, GSMEM>>>(
        oh, ph, b_proj, out, M, E, E);
}

// round 16
// speedup vs baseline: 1.0096x; 1.0096x over previous
#include <cuda_runtime.h>
#include <cuda_fp16.h>
#include <cstdint>

#define BATCH 2
#define SEQ 2048
#define NEMBD 1024
#define NHEAD 16
#define HDIM 64
#define WINDOW 256
#define ATT_SCALE 0.125f   // 1/sqrt(64)

// ---------------- device scratch (allocation-free rule) ----------------
__device__ __half g_kvh[(size_t)4096 * 3072];      // qkv fp16
__device__ __half g_ah[(size_t)4096 * 1024];       // hidden fp16
__device__ __half g_wh[(size_t)1024 * 3072];       // w_attn fp16 [K,N]
__device__ __half g_ph[(size_t)1024 * 1024];       // w_proj fp16 [K,N]
__device__ __half g_oh[(size_t)4096 * 1024];       // attn out fp16

// ---------------- helpers ----------------
__device__ __forceinline__ uint32_t smem_u32(const void* p) {
    uint32_t a;
    asm("{ .reg .u64 t; cvta.to.shared.u64 t, %1; cvt.u32.u64 %0, t; }"
        : "=r"(a) : "l"(p));
    return a;
}
__device__ __forceinline__ uint32_t pkh2(float a, float b) {
    __half2 h = __floats2half2_rn(a, b);
    return *(uint32_t*)&h;
}
__device__ __forceinline__ void mma16816h(float* c, const uint32_t* a, const uint32_t* b) {
    asm volatile(
        "mma.sync.aligned.m16n8k16.row.col.f32.f16.f16.f32 "
        "{%0,%1,%2,%3},{%4,%5,%6,%7},{%8,%9},{%0,%1,%2,%3};"
        : "+f"(c[0]), "+f"(c[1]), "+f"(c[2]), "+f"(c[3])
        : "r"(a[0]), "r"(a[1]), "r"(a[2]), "r"(a[3]), "r"(b[0]), "r"(b[1]));
}
__device__ __forceinline__ void ldsm4(uint32_t* r, uint32_t addr) {
    asm volatile("ldmatrix.sync.aligned.m8n8.x4.shared.b16 {%0,%1,%2,%3}, [%4];"
                 : "=r"(r[0]), "=r"(r[1]), "=r"(r[2]), "=r"(r[3]) : "r"(addr));
}
__device__ __forceinline__ void ldsm4t(uint32_t* r, uint32_t addr) {
    asm volatile("ldmatrix.sync.aligned.m8n8.x4.trans.shared.b16 {%0,%1,%2,%3}, [%4];"
                 : "=r"(r[0]), "=r"(r[1]), "=r"(r[2]), "=r"(r[3]) : "r"(addr));
}
__device__ __forceinline__ void cpa16(uint32_t saddr, const void* gaddr) {
    asm volatile("cp.async.cg.shared.global [%0], [%1], 16;" :: "r"(saddr), "l"(gaddr));
}
#define CP_COMMIT() asm volatile("cp.async.commit_group;")
#define CP_WAIT0()  asm volatile("cp.async.wait_group 0;")
#define CP_WAIT1()  asm volatile("cp.async.wait_group 1;")

// SW128 swizzle for 128B rows
__device__ __forceinline__ uint32_t swz(int row, int col) {
    return (uint32_t)(row * 128 + (col ^ ((row & 7) << 4)));
}
__device__ __forceinline__ float qmax(float v) {
    v = fmaxf(v, __shfl_xor_sync(0xFFFFFFFFu, v, 1));
    v = fmaxf(v, __shfl_xor_sync(0xFFFFFFFFu, v, 2));
    return v;
}
__device__ __forceinline__ float qsum(float v) {
    v += __shfl_xor_sync(0xFFFFFFFFu, v, 1);
    v += __shfl_xor_sync(0xFFFFFFFFu, v, 2);
    return v;
}

// ===========================================================================
// merged fp32 -> fp16 conversion: hidden | w_attn | w_proj in ONE launch
// ===========================================================================
#define CVT_N1 (4096 * 1024 / 4)
#define CVT_N2 (1024 * 3072 / 4)
#define CVT_N3 (1024 * 1024 / 4)

__global__ void cvt_all_kernel(const float* __restrict__ s1, __half* __restrict__ d1,
                               const float* __restrict__ s2, __half* __restrict__ d2,
                               const float* __restrict__ s3, __half* __restrict__ d3) {
    int i = blockIdx.x * blockDim.x + threadIdx.x;
    const float* src; __half* dst;
    if (i < CVT_N1)                { src = s1; dst = d1; }
    else if (i < CVT_N1 + CVT_N2)  { src = s2; dst = d2; i -= CVT_N1; }
    else if (i < CVT_N1 + CVT_N2 + CVT_N3) { src = s3; dst = d3; i -= CVT_N1 + CVT_N2; }
    else return;
    float4 v = *(const float4*)(src + (size_t)i * 4);
    uint2 o;
    o.x = pkh2(v.x, v.y);
    o.y = pkh2(v.z, v.w);
    *(uint2*)(dst + (size_t)i * 4) = o;
}

// ===========================================================================
// QKV GEMM (R13 config, unchanged): CTA 128M x 64N, 256 threads, fp16 out.
// ===========================================================================
#define Q_ST_A  0
#define Q_ST_B  16384
#define Q_ST_SZ 24576
#define QSMEM   (2 * Q_ST_SZ)

__global__ __launch_bounds__(256, 1)
void gemm_qkv_kernel(const __half* __restrict__ A, const __half* __restrict__ B,
                     const float* __restrict__ bias, __half* __restrict__ Ch,
                     int M, int N, int K) {
    extern __shared__ char sm[];
    const uint32_t sb = smem_u32(sm);
    const int tid = threadIdx.x, lane = tid & 31, wid = tid >> 5;
    const int m0 = blockIdx.y * 128, n0 = blockIdx.x * 64;
    const int wm = wid >> 1, wn = wid & 1;
    const int l15 = lane & 15, chi = (lane >> 4) * 16;
    const int lrow = tid >> 3, lc = tid & 7;
    const int NT = K / 64;

    float acc[2][4][4];
#pragma unroll
    for (int i = 0; i < 2; i++)
#pragma unroll
        for (int j = 0; j < 4; j++)
#pragma unroll
            for (int r = 0; r < 4; r++) acc[i][j][r] = 0.f;

    auto load_stage = [&](int s, int kt) {
        const uint32_t sbase = sb + s * Q_ST_SZ;
        const size_t gk = (size_t)kt * 64 + lc * 8;
#pragma unroll
        for (int i = 0; i < 4; i++) {
            const int row = lrow + i * 32;
            cpa16(sbase + Q_ST_A + swz(row, lc * 16), A + (size_t)(m0 + row) * K + gk);
        }
#pragma unroll
        for (int i = 0; i < 2; i++) {
            const int c = tid + i * 256;
            const int r = c >> 3;
            const int nch = c & 7;
            cpa16(sbase + Q_ST_B + swz(r, nch * 16),
                  B + (size_t)(kt * 64 + r) * N + n0 + nch * 8);
        }
    };

    uint32_t Af[2][2][4], Bf[2][2][4];
    auto load_frags = [&](int fb, uint32_t abase, int ks) {
        const int cb = ks * 32 + chi;
#pragma unroll
        for (int mt = 0; mt < 2; mt++)
            ldsm4(Af[fb][mt], abase + Q_ST_A + swz(wm * 32 + mt * 16 + l15, cb));
        const int bcol = wn * 64;
#pragma unroll
        for (int sub = 0; sub < 2; sub++)
            ldsm4t(Bf[fb][sub], abase + Q_ST_B + swz(ks * 16 + l15, bcol + sub * 32 + chi));
    };

    load_stage(0, 0); CP_COMMIT();
    load_stage(1, 1); CP_COMMIT();

    for (int t = 0; t < NT; t++) {
        const int s = t & 1;
        CP_WAIT1();
        __syncthreads();

        const uint32_t abase = sb + s * Q_ST_SZ;
        load_frags(0, abase, 0);
#pragma unroll
        for (int ks = 0; ks < 4; ks++) {
            const int cur = ks & 1;
            if (ks < 3) load_frags(cur ^ 1, abase, ks + 1);
#pragma unroll
            for (int mt = 0; mt < 2; mt++)
#pragma unroll
                for (int nt = 0; nt < 4; nt++) {
                    uint32_t b[2] = { Bf[cur][nt >> 1][(nt & 1) * 2],
                                      Bf[cur][nt >> 1][(nt & 1) * 2 + 1] };
                    mma16816h(acc[mt][nt], Af[cur][mt], b);
                }
        }
        __syncthreads();
        if (t + 2 < NT) { load_stage(s, t + 2); CP_COMMIT(); }
    }

    const int g = lane >> 2, tig = lane & 3;
#pragma unroll
    for (int mt = 0; mt < 2; mt++) {
#pragma unroll
        for (int nt = 0; nt < 4; nt++) {
            int row0 = m0 + wm * 32 + mt * 16 + g;
            int col  = n0 + wn * 32 + nt * 8 + tig * 2;
            float2 bb = *(const float2*)(bias + col);
            *(uint32_t*)(Ch + (size_t)row0 * N + col) =
                pkh2(acc[mt][nt][0] + bb.x, acc[mt][nt][1] + bb.y);
            *(uint32_t*)(Ch + (size_t)(row0 + 8) * N + col) =
                pkh2(acc[mt][nt][2] + bb.x, acc[mt][nt][3] + bb.y);
        }
    }
}

// ===========================================================================
// proj GEMM (R13 config, reverted): CTA 128x128, 256 threads, fp32 out.
// ===========================================================================
#define ST_A  0
#define ST_B  16384
#define ST_SZ 32768
#define GSMEM (2 * ST_SZ)

__global__ __launch_bounds__(256, 1)
void gemm_h_kernel(const __half* __restrict__ A, const __half* __restrict__ B,
                   const float* __restrict__ bias, float* __restrict__ C,
                   int M, int N, int K) {
    extern __shared__ char sm[];
    const uint32_t sb = smem_u32(sm);
    const int tid = threadIdx.x, lane = tid & 31, wid = tid >> 5;
    const int m0 = blockIdx.y * 128, n0 = blockIdx.x * 128;
    const int wm = wid >> 2, wn = wid & 3;
    const int l15 = lane & 15, chi = (lane >> 4) * 16;
    const int lrow = tid >> 3, lc = tid & 7;
    const int NT = K / 64;

    float acc[4][4][4];
#pragma unroll
    for (int i = 0; i < 4; i++)
#pragma unroll
        for (int j = 0; j < 4; j++)
#pragma unroll
            for (int r = 0; r < 4; r++) acc[i][j][r] = 0.f;

    auto load_stage = [&](int s, int kt) {
        const uint32_t sbase = sb + s * ST_SZ;
        const size_t gk = (size_t)kt * 64 + lc * 8;
#pragma unroll
        for (int i = 0; i < 4; i++) {
            const int row = lrow + i * 32;
            cpa16(sbase + ST_A + swz(row, lc * 16), A + (size_t)(m0 + row) * K + gk);
        }
#pragma unroll
        for (int i = 0; i < 4; i++) {
            const int c = tid + i * 256;
            const int r = c >> 4;
            const int nch = c & 15;
            const uint32_t so = ST_B + (nch >> 3) * 8192 + swz(r, (nch & 7) * 16);
            cpa16(sbase + so, B + (size_t)(kt * 64 + r) * N + n0 + nch * 8);
        }
    };

    uint32_t Af[2][4][4], Bf[2][2][4];
    auto load_frags = [&](int fb, uint32_t abase, int ks) {
        const int cb = ks * 32 + chi;
#pragma unroll
        for (int mt = 0; mt < 4; mt++)
            ldsm4(Af[fb][mt], abase + ST_A + swz(wm * 64 + mt * 16 + l15, cb));
        const uint32_t bbase = abase + ST_B + (wn >> 1) * 8192;
        const int bcol = (wn & 1) * 64;
#pragma unroll
        for (int sub = 0; sub < 2; sub++)
            ldsm4t(Bf[fb][sub], bbase + swz(ks * 16 + l15, bcol + sub * 32 + chi));
    };

    load_stage(0, 0); CP_COMMIT();
    load_stage(1, 1); CP_COMMIT();

    for (int t = 0; t < NT; t++) {
        const int s = t & 1;
        CP_WAIT1();
        __syncthreads();

        const uint32_t abase = sb + s * ST_SZ;
        load_frags(0, abase, 0);
#pragma unroll
        for (int ks = 0; ks < 4; ks++) {
            const int cur = ks & 1;
            if (ks < 3) load_frags(cur ^ 1, abase, ks + 1);
#pragma unroll
            for (int mt = 0; mt < 4; mt++)
#pragma unroll
                for (int nt = 0; nt < 4; nt++) {
                    uint32_t b[2] = { Bf[cur][nt >> 1][(nt & 1) * 2],
                                      Bf[cur][nt >> 1][(nt & 1) * 2 + 1] };
                    mma16816h(acc[mt][nt], Af[cur][mt], b);
                }
        }
        __syncthreads();
        if (t + 2 < NT) { load_stage(s, t + 2); CP_COMMIT(); }
    }

    const int g = lane >> 2, tig = lane & 3;
#pragma unroll
    for (int mt = 0; mt < 4; mt++) {
#pragma unroll
        for (int nt = 0; nt < 4; nt++) {
            int row0 = m0 + wm * 64 + mt * 16 + g;
            int col  = n0 + wn * 32 + nt * 8 + tig * 2;
            float2 bb = *(const float2*)(bias + col);
            *(float2*)(C + (size_t)row0 * N + col) =
                make_float2(acc[mt][nt][0] + bb.x, acc[mt][nt][1] + bb.y);
            *(float2*)(C + (size_t)(row0 + 8) * N + col) =
                make_float2(acc[mt][nt][2] + bb.x, acc[mt][nt][3] + bb.y);
        }
    }
}

// ===========================================================================
// Flash attention: 128 queries per CTA, 8 warps, 256 threads.
// R13 masked path (with clamp) applied to EVERY tile. m initialized to 0
// so fully-masked tiles contribute exactly 0 (exp(-1e30 - max(0,.)) == 0).
// ===========================================================================
#define AQ_OFF  0                              // Q staging: 16KB (128 rows)
#define AS_OFF  16384                          // stage s at 16384 + s*16384
#define AS_SZ   16384                          // K (8KB) + V (8KB)
#define A_SMEM  (16384 + 2 * 16384)            // 49152

__global__ __launch_bounds__(256)
void attn_mma_kernel(const __half* __restrict__ qkv, __half* __restrict__ oh) {
    extern __shared__ char sm[];
    const uint32_t sb = smem_u32(sm);
    const int b = blockIdx.z, h = blockIdx.y, qs = blockIdx.x * 128;
    const int tid = threadIdx.x, lane = tid & 31, wid = tid >> 5;   // wid 0..7
    const int l15 = lane & 15, chi = (lane >> 4) * 16;
    const int g = lane >> 2, tig = lane & 3;
    const size_t RS = 3 * NEMBD;
    const int hcol = h * HDIM;

    const int kt0 = (qs - WINDOW < 0) ? 0 : qs - WINDOW;
    const int ktend = qs + 64;                 // last tile (rows up to qs+127)
    const int ntiles = (ktend - kt0) / 64 + 1;

    // K/V tile async load into stage s (buf: 0 K, 1 V); 1024 chunks, 256 thr
    auto load_kv = [&](int s, int kt) {
        const uint32_t sbase = sb + AS_OFF + s * AS_SZ;
#pragma unroll
        for (int i = 0; i < 4; i++) {
            int idx = tid + i * 256;               // 0..1023
            int buf = idx >> 9;                    // 0 K, 1 V
            int rem = idx & 511;
            int r = rem >> 3, c = rem & 7;
            const __half* src = qkv
                + ((size_t)(b * SEQ + kt + r)) * RS + NEMBD + buf * NEMBD + hcol + c * 8;
            cpa16(sbase + buf * 8192 + swz(r, c * 16), src);
        }
    };

    load_kv(0, kt0); CP_COMMIT();
    // stage Q (128 rows x 128B = 1024 chunks) while K/V flies
#pragma unroll
    for (int i = 0; i < 4; i++) {
        int idx = tid + i * 256;                   // 0..1023
        int r = idx >> 3, c = idx & 7;
        const __half* src = qkv + ((size_t)(b * SEQ + qs + r)) * RS + hcol + c * 8;
        *(uint4*)(sm + AQ_OFF + swz(r, c * 16)) = *(const uint4*)src;
    }
    __syncthreads();
    uint32_t Qf[4][4];
#pragma unroll
    for (int kk = 0; kk < 4; kk++)
        ldsm4(Qf[kk], sb + AQ_OFF + swz(wid * 16 + l15, kk * 32 + chi));

    float o[8][4];
#pragma unroll
    for (int i = 0; i < 8; i++)
#pragma unroll
        for (int r = 0; r < 4; r++) o[i][r] = 0.f;
    // m init 0 (not -1e30): masked-only tiles then give exp(-1e30 - m) == 0
    // exactly. Softmax shift becomes max(0, rowmax) — shift-invariant, and
    // |s| <= ~4 so exp stays in range either way.
    float m0 = 0.f, m1 = 0.f, l0 = 0.f, l1 = 0.f;
    const int row0 = qs + wid * 16 + g, row1 = row0 + 8;

    for (int it = 0; it < ntiles; it++) {
        const int kt = kt0 + it * 64;
        const int cur = it & 1;
        const bool pf = (it + 1 < ntiles);
        if (pf) { load_kv(cur ^ 1, kt + 64); CP_COMMIT(); }
        if (pf) { CP_WAIT1(); } else { CP_WAIT0(); }
        __syncthreads();

        const uint32_t kbase = sb + AS_OFF + cur * AS_SZ;

        // ---- S = Q K^T ----
        float s[8][4];
#pragma unroll
        for (int i = 0; i < 8; i++)
#pragma unroll
            for (int r = 0; r < 4; r++) s[i][r] = 0.f;
#pragma unroll
        for (int kk = 0; kk < 4; kk++) {
            const int cb = kk * 32 + chi;
            uint32_t Kf[4][4];
#pragma unroll
            for (int bt = 0; bt < 4; bt++)
                ldsm4(Kf[bt], kbase + swz(bt * 16 + l15, cb));
#pragma unroll
            for (int nt = 0; nt < 8; nt++) {
                uint32_t bfr[2] = { Kf[nt >> 1][nt & 1], Kf[nt >> 1][(nt & 1) + 2] };
                mma16816h(s[nt], Qf[kk], bfr);
            }
        }

        // ---- mask (R13 path, clamp kept) + online softmax ----
        float mx0 = -1e30f, mx1 = -1e30f;
#pragma unroll
        for (int nt = 0; nt < 8; nt++) {
            int j0 = kt + nt * 8 + tig * 2, j1 = j0 + 1;
            float v;
            v = fminf(fmaxf(s[nt][0] * ATT_SCALE, -10000.f), 10000.f);
            v = (j0 <= row0 && j0 > row0 - WINDOW) ? v : -1e30f;
            s[nt][0] = v; mx0 = fmaxf(mx0, v);
            v = fminf(fmaxf(s[nt][1] * ATT_SCALE, -10000.f), 10000.f);
            v = (j1 <= row0 && j1 > row0 - WINDOW) ? v : -1e30f;
            s[nt][1] = v; mx0 = fmaxf(mx0, v);
            v = fminf(fmaxf(s[nt][2] * ATT_SCALE, -10000.f), 10000.f);
            v = (j0 <= row1 && j0 > row1 - WINDOW) ? v : -1e30f;
            s[nt][2] = v; mx1 = fmaxf(mx1, v);
            v = fminf(fmaxf(s[nt][3] * ATT_SCALE, -10000.f), 10000.f);
            v = (j1 <= row1 && j1 > row1 - WINDOW) ? v : -1e30f;
            s[nt][3] = v; mx1 = fmaxf(mx1, v);
        }
        mx0 = qmax(mx0); mx1 = qmax(mx1);
        const float m0n = fmaxf(m0, mx0), m1n = fmaxf(m1, mx1);   // >= 0 always
        const float c0 = __expf(m0 - m0n), c1 = __expf(m1 - m1n);

        uint32_t ph01[8], ph23[8];
        float sum0 = 0.f, sum1 = 0.f;
#pragma unroll
        for (int nt = 0; nt < 8; nt++) {
            float p0 = __expf(s[nt][0] - m0n), p1 = __expf(s[nt][1] - m0n);
            float p2 = __expf(s[nt][2] - m1n), p3 = __expf(s[nt][3] - m1n);
            sum0 += p0 + p1; sum1 += p2 + p3;
            ph01[nt] = pkh2(p0, p1);
            ph23[nt] = pkh2(p2, p3);
        }
        sum0 = qsum(sum0); sum1 = qsum(sum1);
        l0 = l0 * c0 + sum0; l1 = l1 * c1 + sum1;
        m0 = m0n; m1 = m1n;
#pragma unroll
        for (int i = 0; i < 8; i++) {
            o[i][0] *= c0; o[i][1] *= c0; o[i][2] *= c1; o[i][3] *= c1;
        }

        // ---- O += P V ----
#pragma unroll
        for (int kk = 0; kk < 4; kk++) {
            uint32_t pa[4] = { ph01[2 * kk], ph23[2 * kk], ph01[2 * kk + 1], ph23[2 * kk + 1] };
            uint32_t Vf[4][4];
#pragma unroll
            for (int db = 0; db < 4; db++)
                ldsm4t(Vf[db], kbase + 8192 + swz(kk * 16 + l15, db * 32 + chi));
#pragma unroll
            for (int dnt = 0; dnt < 8; dnt++) {
                uint32_t bfr[2] = { Vf[dnt >> 1][(dnt & 1) * 2], Vf[dnt >> 1][(dnt & 1) * 2 + 1] };
                mma16816h(o[dnt], pa, bfr);
            }
        }
        __syncthreads();
    }

    const float i0 = 1.f / l0, i1 = 1.f / l1;
    const size_t tok0 = (size_t)(b * SEQ) + row0;
#pragma unroll
    for (int dnt = 0; dnt < 8; dnt++) {
        int col = hcol + dnt * 8 + tig * 2;
        *(uint32_t*)(oh + tok0 * NEMBD + col)       = pkh2(o[dnt][0] * i0, o[dnt][1] * i0);
        *(uint32_t*)(oh + (tok0 + 8) * NEMBD + col) = pkh2(o[dnt][2] * i1, o[dnt][3] * i1);
    }
}

// ---------------------------------------------------------------------------
extern "C" void kernel_launch(void* const* d_in, const int* in_sizes, int n_in,
                              void* d_out, int out_size) {
    const float* hidden = (const float*)d_in[0];
    const float* w_attn = (const float*)d_in[1];
    const float* b_attn = (const float*)d_in[2];
    const float* w_proj = (const float*)d_in[3];
    const float* b_proj = (const float*)d_in[4];
    float* out = (float*)d_out;

    __half *kvh, *ah, *wh, *ph, *oh;
    cudaGetSymbolAddress((void**)&kvh, g_kvh);
    cudaGetSymbolAddress((void**)&ah, g_ah);
    cudaGetSymbolAddress((void**)&wh, g_wh);
    cudaGetSymbolAddress((void**)&ph, g_ph);
    cudaGetSymbolAddress((void**)&oh, g_oh);

    const int M = BATCH * SEQ;       // 4096
    const int E = NEMBD;             // 1024

    cudaFuncSetAttribute(gemm_qkv_kernel,
                         cudaFuncAttributeMaxDynamicSharedMemorySize, QSMEM);
    cudaFuncSetAttribute(gemm_h_kernel,
                         cudaFuncAttributeMaxDynamicSharedMemorySize, GSMEM);
    cudaFuncSetAttribute(attn_mma_kernel,
                         cudaFuncAttributeMaxDynamicSharedMemorySize, A_SMEM);

    // 0) all conversions in one launch
    {
        int total = CVT_N1 + CVT_N2 + CVT_N3;
        cvt_all_kernel<<<(total + 255) / 256, 256>>>(hidden, ah, w_attn, wh, w_proj, ph);
    }

    // 1) QKV projection (128x64 tiles)
    gemm_qkv_kernel<<<dim3(3 * E / 64, M / 128), 256, QSMEM>>>(
        ah, wh, b_attn, kvh, M, 3 * E, E);
    // 2) flash attention (128 queries/CTA) -> fp16
    attn_mma_kernel<<<dim3(SEQ / 128, NHEAD, BATCH), 256, A_SMEM>>>(kvh, oh);
    // 3) output projection (128x128 tiles, R13-proven) -> fp32
    gemm_h_kernel<<<dim3(E / 128, M / 128), 256, GSMEM>>>(
        oh, ph, b_proj, out, M, E, E);
}